// round 7
// baseline (speedup 1.0000x reference)
#include <cuda_runtime.h>
#include <math.h>

#define SEQ   2097152
#define C     8192            // number of chunks
#define L     256             // steps per chunk (C*L == SEQ)
#define MPRE  32              // stored prefix length (merge-detect window)
#define KPB   16              // chunks per block in k1
#define TPB   256             // threads per k1 block
#define NSUP  1024            // fixpoint threads
#define SUBS  (C / NSUP)      // 8 chunks per fixpoint thread

// ---------------- scratch (static device globals; no allocation) ------------
__device__ float2 g_cpre[C * MPRE];   // c prefix, chunk-major [k*MPRE + s]
__device__ float2 g_ypre[C * MPRE];   // pass-A y prefix, chunk-major
__device__ float2 g_exit[C];          // pass-A exit state per chunk
__device__ float2 g_yin[C];           // final entry state per chunk (k2)

// Fold raw weights into the cell: c_t = M x_t + d ; y_t = relu(B y_{t-1} + c_t)
__device__ __forceinline__ void fold_cell(const float* __restrict__ W1,
                                          const float* __restrict__ b1,
                                          const float* __restrict__ Wd,
                                          const float* __restrict__ bd,
                                          float* m, float* d, float* B) {
    #pragma unroll
    for (int h = 0; h < 2; ++h) {
        float a0 = __ldg(&Wd[h * 4 + 0]);
        float a1 = __ldg(&Wd[h * 4 + 1]);
        #pragma unroll
        for (int i = 0; i < 4; ++i)
            m[h * 4 + i] = a0 * __ldg(&W1[i]) + a1 * __ldg(&W1[4 + i]);
        d[h] = a0 * __ldg(&b1[0]) + a1 * __ldg(&b1[1]) + __ldg(&bd[h]);
        B[h * 2 + 0] = __ldg(&Wd[h * 4 + 2]);
        B[h * 2 + 1] = __ldg(&Wd[h * 4 + 3]);
    }
}

__device__ __forceinline__ float2 sigmoid2(float y0, float y1,
                                           float W20, float W21, float W22, float W23,
                                           float bo0, float bo1) {
    float z0 = fmaf(W20, y0, fmaf(W21, y1, bo0));
    float z1 = fmaf(W22, y0, fmaf(W23, y1, bo1));
    return make_float2(1.0f / (1.0f + __expf(-z0)), 1.0f / (1.0f + __expf(-z1)));
}

// ---------------- K1: x -> c -> pass-A scan -> provisional sigmoid out ------
// Block handles 16 chunks = 4096 consecutive timesteps.
__global__ void __launch_bounds__(TPB) k1_scan(const float4* __restrict__ x,
                                               const float* __restrict__ W1,
                                               const float* __restrict__ b1,
                                               const float* __restrict__ Wd,
                                               const float* __restrict__ bd,
                                               const float* __restrict__ W2,
                                               const float* __restrict__ b2,
                                               float2* __restrict__ out) {
    __shared__ float2 tile[L * 17];          // [s*17 + kk]
    const int tid = threadIdx.x;
    const int k0  = blockIdx.x * KPB;
    const size_t tbase = (size_t)k0 * L;

    float m[8], d[2], B[4];
    fold_cell(W1, b1, Wd, bd, m, d, B);

    // phase 1: coalesced x reads -> c -> tile
    #pragma unroll
    for (int r = 0; r < 16; ++r) {
        int i = r * TPB + tid;               // i = kk*256 + s
        float4 xv = __ldcs(&x[tbase + i]);
        int kk = i >> 8, s = i & 255;
        float c0 = fmaf(m[0], xv.x, fmaf(m[1], xv.y, fmaf(m[2], xv.z, fmaf(m[3], xv.w, d[0]))));
        float c1 = fmaf(m[4], xv.x, fmaf(m[5], xv.y, fmaf(m[6], xv.z, fmaf(m[7], xv.w, d[1]))));
        tile[s * 17 + kk] = make_float2(c0, c1);
    }
    __syncthreads();

    // phase 1b: store c prefix (chunk-major, coalesced per chunk)
    #pragma unroll
    for (int r = 0; r < 2; ++r) {
        int j = r * TPB + tid;               // j in [0, 512)
        int s = j & (MPRE - 1), kk = j >> 5;
        g_cpre[(size_t)(k0 + kk) * MPRE + s] = tile[s * 17 + kk];
    }
    __syncthreads();

    // phase 2: 16 threads scan their chunk from y = 0, overwrite tile with y
    if (tid < KPB) {
        float y0 = 0.f, y1 = 0.f;
        for (int s = 0; s < L; ++s) {
            float2 c = tile[s * 17 + tid];
            float n0 = fmaxf(fmaf(B[1], y1, fmaf(B[0], y0, c.x)), 0.f);
            float n1 = fmaxf(fmaf(B[3], y1, fmaf(B[2], y0, c.y)), 0.f);
            y0 = n0; y1 = n1;
            tile[s * 17 + tid] = make_float2(y0, y1);
        }
        g_exit[k0 + tid] = make_float2(y0, y1);
    }
    __syncthreads();

    // phase 3a: store y prefix
    #pragma unroll
    for (int r = 0; r < 2; ++r) {
        int j = r * TPB + tid;
        int s = j & (MPRE - 1), kk = j >> 5;
        g_ypre[(size_t)(k0 + kk) * MPRE + s] = tile[s * 17 + kk];
    }

    // phase 3b: provisional sigmoid output, coalesced
    const float W20 = __ldg(&W2[0]), W21 = __ldg(&W2[1]);
    const float W22 = __ldg(&W2[2]), W23 = __ldg(&W2[3]);
    const float bo0 = __ldg(&b2[0]), bo1 = __ldg(&b2[1]);
    #pragma unroll
    for (int r = 0; r < 16; ++r) {
        int i = r * TPB + tid;
        int kk = i >> 8, s = i & 255;
        float2 y = tile[s * 17 + kk];
        __stcs(&out[tbase + i], sigmoid2(y.x, y.y, W20, W21, W22, W23, bo0, bo1));
    }
}

// ---------------- K2: boundary fixpoint + fused patch epilogue --------------
// One block, 1024 threads; thread T owns chunks [8T, 8T+8) serially.
// Merge-early-exit against the stored prefix; rare no-merge fallback
// recomputes c from x on the fly (exact full replay — never incorrect).
__global__ void __launch_bounds__(NSUP) k2_fixpoint(const float4* __restrict__ x,
                                                    const float* __restrict__ W1,
                                                    const float* __restrict__ b1,
                                                    const float* __restrict__ Wd,
                                                    const float* __restrict__ bd,
                                                    const float* __restrict__ W2,
                                                    const float* __restrict__ b2,
                                                    float2* __restrict__ out) {
    __shared__ float2 bnd[NSUP + 1];
    const int T = threadIdx.x;

    float m[8], d[2], B[4];
    fold_cell(W1, b1, Wd, bd, m, d, B);
    const float B00 = B[0], B01 = B[1], B10 = B[2], B11 = B[3];

    bnd[T] = (T == 0) ? make_float2(0.f, 0.f) : g_exit[T * SUBS - 1];
    if (T == 0) bnd[NSUP] = g_exit[C - 1];

    unsigned prev0 = 0xFFFFFFFFu, prev1 = 0xFFFFFFFFu;  // force first walk
    float2 cached = make_float2(0.f, 0.f);
    __syncthreads();

    for (int iter = 0; iter < NSUP + 2; ++iter) {
        float2 yin = bnd[T];
        float2 old = bnd[T + 1];
        unsigned a0 = __float_as_uint(yin.x);
        unsigned a1 = __float_as_uint(yin.y);

        if (a0 != prev0 || a1 != prev1) {
            prev0 = a0; prev1 = a1;
            float y0 = yin.x, y1 = yin.y;
            for (int j = 0; j < SUBS; ++j) {
                int k = T * SUBS + j;
                g_yin[k] = make_float2(y0, y1);   // entry under current boundaries
                bool merged = false;
                const float2* cp = g_cpre + (size_t)k * MPRE;
                const float2* yp = g_ypre + (size_t)k * MPRE;
                for (int s = 0; s < MPRE; ++s) {
                    float2 c = cp[s];
                    float n0 = fmaxf(fmaf(B01, y1, fmaf(B00, y0, c.x)), 0.f);
                    float n1 = fmaxf(fmaf(B11, y1, fmaf(B10, y0, c.y)), 0.f);
                    y0 = n0; y1 = n1;
                    float2 st = yp[s];
                    if (__float_as_uint(st.x) == __float_as_uint(y0) &&
                        __float_as_uint(st.y) == __float_as_uint(y1)) {
                        float2 e = g_exit[k];     // merged: stored suffix exact
                        y0 = e.x; y1 = e.y;
                        merged = true;
                        break;
                    }
                }
                if (!merged) {                    // fallback: exact full replay
                    const float4* xp = x + (size_t)k * L;
                    for (int s = MPRE; s < L; ++s) {
                        float4 xv = xp[s];
                        float c0 = fmaf(m[0], xv.x, fmaf(m[1], xv.y, fmaf(m[2], xv.z, fmaf(m[3], xv.w, d[0]))));
                        float c1 = fmaf(m[4], xv.x, fmaf(m[5], xv.y, fmaf(m[6], xv.z, fmaf(m[7], xv.w, d[1]))));
                        float n0 = fmaxf(fmaf(B01, y1, fmaf(B00, y0, c0)), 0.f);
                        float n1 = fmaxf(fmaf(B11, y1, fmaf(B10, y0, c1)), 0.f);
                        y0 = n0; y1 = n1;
                    }
                }
            }
            cached = make_float2(y0, y1);
        }

        __syncthreads();                 // reads of bnd done
        bnd[T + 1] = cached;             // unique writer per slot
        int changed = (__float_as_uint(cached.x) != __float_as_uint(old.x)) |
                      (__float_as_uint(cached.y) != __float_as_uint(old.y));
        if (__syncthreads_or(changed) == 0) break;
    }

    // ---- fused patch epilogue: rewrite only the mismatched prefix outputs ----
    const float W20 = __ldg(&W2[0]), W21 = __ldg(&W2[1]);
    const float W22 = __ldg(&W2[2]), W23 = __ldg(&W2[3]);
    const float bo0 = __ldg(&b2[0]), bo1 = __ldg(&b2[1]);

    for (int j = 0; j < SUBS; ++j) {
        int k = T * SUBS + j;
        float2 yin = g_yin[k];
        float y0 = yin.x, y1 = yin.y;
        const float2* cp = g_cpre + (size_t)k * MPRE;
        const float2* yp = g_ypre + (size_t)k * MPRE;
        float2* op = out + (size_t)k * L;
        bool merged = false;
        for (int s = 0; s < MPRE; ++s) {
            float2 c = cp[s];
            float n0 = fmaxf(fmaf(B01, y1, fmaf(B00, y0, c.x)), 0.f);
            float n1 = fmaxf(fmaf(B11, y1, fmaf(B10, y0, c.y)), 0.f);
            y0 = n0; y1 = n1;
            float2 st = yp[s];
            if (__float_as_uint(st.x) == __float_as_uint(y0) &&
                __float_as_uint(st.y) == __float_as_uint(y1)) {
                merged = true;            // provisional output exact from here
                break;
            }
            op[s] = sigmoid2(y0, y1, W20, W21, W22, W23, bo0, bo1);
        }
        if (!merged) {                    // rare: rewrite the whole chunk tail
            const float4* xp = x + (size_t)k * L;
            for (int s = MPRE; s < L; ++s) {
                float4 xv = xp[s];
                float c0 = fmaf(m[0], xv.x, fmaf(m[1], xv.y, fmaf(m[2], xv.z, fmaf(m[3], xv.w, d[0]))));
                float c1 = fmaf(m[4], xv.x, fmaf(m[5], xv.y, fmaf(m[6], xv.z, fmaf(m[7], xv.w, d[1]))));
                float n0 = fmaxf(fmaf(B01, y1, fmaf(B00, y0, c0)), 0.f);
                float n1 = fmaxf(fmaf(B11, y1, fmaf(B10, y0, c1)), 0.f);
                y0 = n0; y1 = n1;
                op[s] = sigmoid2(y0, y1, W20, W21, W22, W23, bo0, bo1);
            }
        }
    }
}

// ---------------- launch -----------------------------------------------------
extern "C" void kernel_launch(void* const* d_in, const int* in_sizes, int n_in,
                              void* d_out, int out_size) {
    const float* x  = (const float*)d_in[0];
    const float* W1 = (const float*)d_in[1];
    const float* b1 = (const float*)d_in[2];
    const float* Wd = (const float*)d_in[3];
    const float* bd = (const float*)d_in[4];
    const float* W2 = (const float*)d_in[5];
    const float* b2 = (const float*)d_in[6];
    (void)in_sizes; (void)n_in; (void)out_size;

    k1_scan<<<C / KPB, TPB>>>((const float4*)x, W1, b1, Wd, bd, W2, b2, (float2*)d_out);
    k2_fixpoint<<<1, NSUP>>>((const float4*)x, W1, b1, Wd, bd, W2, b2, (float2*)d_out);
}

// round 8
// speedup vs baseline: 3.5366x; 3.5366x over previous
#include <cuda_runtime.h>
#include <math.h>

#define SEQ   2097152
#define C     8192            // number of chunks
#define L     256             // steps per chunk (C*L == SEQ)
#define MPRE  32              // merge-detect window (stored y prefix length)
#define KPB   16              // chunks per block in k1
#define TPB   256             // threads per k1 block

// ---------------- scratch (static device globals; no allocation) ------------
__device__ float2        g_ypre[C * MPRE]; // pass-A y prefix, chunk-major
__device__ float2        g_exit[C];        // pass-A exit per chunk (exact if merged)
__device__ float2        g_exit2[C];       // exit from verify's full-replay fallback
__device__ unsigned char g_flag[C];        // 1 = merged under candidate entry
__device__ int           g_nfail;          // count of unmerged chunks

// Fold raw weights: c_t = M x_t + d ; y_t = relu(B y_{t-1} + c_t)
// Deterministic identical arithmetic in every kernel -> bitwise-identical c.
__device__ __forceinline__ void fold_cell(const float* __restrict__ W1,
                                          const float* __restrict__ b1,
                                          const float* __restrict__ Wd,
                                          const float* __restrict__ bd,
                                          float* m, float* d, float* B) {
    #pragma unroll
    for (int h = 0; h < 2; ++h) {
        float a0 = __ldg(&Wd[h * 4 + 0]);
        float a1 = __ldg(&Wd[h * 4 + 1]);
        #pragma unroll
        for (int i = 0; i < 4; ++i)
            m[h * 4 + i] = a0 * __ldg(&W1[i]) + a1 * __ldg(&W1[4 + i]);
        d[h] = a0 * __ldg(&b1[0]) + a1 * __ldg(&b1[1]) + __ldg(&bd[h]);
        B[h * 2 + 0] = __ldg(&Wd[h * 4 + 2]);
        B[h * 2 + 1] = __ldg(&Wd[h * 4 + 3]);
    }
}

__device__ __forceinline__ float2 sigmoid2(float y0, float y1,
                                           float W20, float W21, float W22, float W23,
                                           float bo0, float bo1) {
    float z0 = fmaf(W20, y0, fmaf(W21, y1, bo0));
    float z1 = fmaf(W22, y0, fmaf(W23, y1, bo1));
    return make_float2(1.0f / (1.0f + __expf(-z0)), 1.0f / (1.0f + __expf(-z1)));
}

__device__ __forceinline__ void step_from_x(float4 xv, const float* m, const float* d,
                                            const float* B, float& y0, float& y1) {
    float c0 = fmaf(m[0], xv.x, fmaf(m[1], xv.y, fmaf(m[2], xv.z, fmaf(m[3], xv.w, d[0]))));
    float c1 = fmaf(m[4], xv.x, fmaf(m[5], xv.y, fmaf(m[6], xv.z, fmaf(m[7], xv.w, d[1]))));
    float n0 = fmaxf(fmaf(B[1], y1, fmaf(B[0], y0, c0)), 0.f);
    float n1 = fmaxf(fmaf(B[3], y1, fmaf(B[2], y0, c1)), 0.f);
    y0 = n0; y1 = n1;
}

// ---------------- K1: x -> c -> pass-A scan -> provisional sigmoid out ------
__global__ void __launch_bounds__(TPB) k1_scan(const float4* __restrict__ x,
                                               const float* __restrict__ W1,
                                               const float* __restrict__ b1,
                                               const float* __restrict__ Wd,
                                               const float* __restrict__ bd,
                                               const float* __restrict__ W2,
                                               const float* __restrict__ b2,
                                               float2* __restrict__ out) {
    __shared__ float2 tile[L * 17];          // [s*17 + kk]
    const int tid = threadIdx.x;
    const int k0  = blockIdx.x * KPB;
    const size_t tbase = (size_t)k0 * L;

    if (blockIdx.x == 0 && tid == 0) g_nfail = 0;   // reset for graph replay

    float m[8], d[2], B[4];
    fold_cell(W1, b1, Wd, bd, m, d, B);

    // phase 1: coalesced x reads -> c -> smem tile
    #pragma unroll
    for (int r = 0; r < 16; ++r) {
        int i = r * TPB + tid;               // i = kk*256 + s
        float4 xv = __ldcs(&x[tbase + i]);
        int kk = i >> 8, s = i & 255;
        float c0 = fmaf(m[0], xv.x, fmaf(m[1], xv.y, fmaf(m[2], xv.z, fmaf(m[3], xv.w, d[0]))));
        float c1 = fmaf(m[4], xv.x, fmaf(m[5], xv.y, fmaf(m[6], xv.z, fmaf(m[7], xv.w, d[1]))));
        tile[s * 17 + kk] = make_float2(c0, c1);
    }
    __syncthreads();

    // phase 2: 16 threads scan their chunk from y = 0, overwrite tile with y
    if (tid < KPB) {
        float y0 = 0.f, y1 = 0.f;
        #pragma unroll 4
        for (int s = 0; s < L; ++s) {
            float2 c = tile[s * 17 + tid];
            float n0 = fmaxf(fmaf(B[1], y1, fmaf(B[0], y0, c.x)), 0.f);
            float n1 = fmaxf(fmaf(B[3], y1, fmaf(B[2], y0, c.y)), 0.f);
            y0 = n0; y1 = n1;
            tile[s * 17 + tid] = make_float2(y0, y1);
        }
        g_exit[k0 + tid] = make_float2(y0, y1);
    }
    __syncthreads();

    // phase 3a: store y prefix (chunk-major; coalesced: warp covers one chunk)
    #pragma unroll
    for (int r = 0; r < 2; ++r) {
        int j = r * TPB + tid;               // j in [0, 512)
        int s = j & (MPRE - 1), kk = j >> 5;
        g_ypre[(size_t)(k0 + kk) * MPRE + s] = tile[s * 17 + kk];
    }

    // phase 3b: provisional sigmoid output, coalesced
    const float W20 = __ldg(&W2[0]), W21 = __ldg(&W2[1]);
    const float W22 = __ldg(&W2[2]), W23 = __ldg(&W2[3]);
    const float bo0 = __ldg(&b2[0]), bo1 = __ldg(&b2[1]);
    #pragma unroll
    for (int r = 0; r < 16; ++r) {
        int i = r * TPB + tid;
        int kk = i >> 8, s = i & 255;
        float2 y = tile[s * 17 + kk];
        __stcs(&out[tbase + i], sigmoid2(y.x, y.y, W20, W21, W22, W23, bo0, bo1));
    }
}

// ---------------- K2: grid-parallel verify + patch ---------------------------
// One thread per chunk. Candidate entry = previous chunk's pass-A exit.
// Walk recomputes c from x (bitwise-identical to k1); on bitwise merge with the
// stored pass-A prefix, the chunk's stored suffix, provisional outputs, and
// g_exit are all exact for this entry (by induction from chunk 0). Steps before
// the merge get their outputs patched. No merge within MPRE -> full exact
// replay of the chunk (outputs rewritten), flagged for the cleanup pass.
__global__ void __launch_bounds__(256) k2_verify(const float4* __restrict__ x,
                                                 const float* __restrict__ W1,
                                                 const float* __restrict__ b1,
                                                 const float* __restrict__ Wd,
                                                 const float* __restrict__ bd,
                                                 const float* __restrict__ W2,
                                                 const float* __restrict__ b2,
                                                 float2* __restrict__ out) {
    const int k = blockIdx.x * blockDim.x + threadIdx.x;
    if (k >= C) return;

    float m[8], d[2], B[4];
    fold_cell(W1, b1, Wd, bd, m, d, B);
    const float W20 = __ldg(&W2[0]), W21 = __ldg(&W2[1]);
    const float W22 = __ldg(&W2[2]), W23 = __ldg(&W2[3]);
    const float bo0 = __ldg(&b2[0]), bo1 = __ldg(&b2[1]);

    float2 e = (k == 0) ? make_float2(0.f, 0.f) : g_exit[k - 1];
    float y0 = e.x, y1 = e.y;

    const float4*  xp = x + (size_t)k * L;
    const float2*  yp = g_ypre + (size_t)k * MPRE;
    float2*        op = out + (size_t)k * L;

    bool merged = false;
    for (int s = 0; s < MPRE; ++s) {
        step_from_x(xp[s], m, d, B, y0, y1);
        float2 st = yp[s];
        if (__float_as_uint(st.x) == __float_as_uint(y0) &&
            __float_as_uint(st.y) == __float_as_uint(y1)) {
            merged = true;                   // suffix + exit already exact
            break;
        }
        op[s] = sigmoid2(y0, y1, W20, W21, W22, W23, bo0, bo1);
    }

    if (merged) {
        g_flag[k] = 1;
    } else {                                 // rare: exact full replay of chunk
        for (int s = MPRE; s < L; ++s) {
            step_from_x(xp[s], m, d, B, y0, y1);
            op[s] = sigmoid2(y0, y1, W20, W21, W22, W23, bo0, bo1);
        }
        g_exit2[k] = make_float2(y0, y1);
        g_flag[k] = 0;
        atomicAdd(&g_nfail, 1);
    }
}

// ---------------- K3: cleanup (fast path: one load, return) ------------------
// Only runs real work if some chunk failed to merge. Propagates the exact state
// sequentially; chunks whose verify entry matches the exact state are skipped
// O(1), others are fully replayed with outputs rewritten. Never incorrect.
__global__ void k3_cleanup(const float4* __restrict__ x,
                           const float* __restrict__ W1,
                           const float* __restrict__ b1,
                           const float* __restrict__ Wd,
                           const float* __restrict__ bd,
                           const float* __restrict__ W2,
                           const float* __restrict__ b2,
                           float2* __restrict__ out) {
    if (threadIdx.x != 0 || blockIdx.x != 0) return;
    if (g_nfail == 0) return;                // expected path

    float m[8], d[2], B[4];
    fold_cell(W1, b1, Wd, bd, m, d, B);
    const float W20 = __ldg(&W2[0]), W21 = __ldg(&W2[1]);
    const float W22 = __ldg(&W2[2]), W23 = __ldg(&W2[3]);
    const float bo0 = __ldg(&b2[0]), bo1 = __ldg(&b2[1]);

    float y0 = 0.f, y1 = 0.f;                // exact state entering chunk k
    for (int k = 0; k < C; ++k) {
        float2 cand = (k == 0) ? make_float2(0.f, 0.f) : g_exit[k - 1];
        if (__float_as_uint(y0) == __float_as_uint(cand.x) &&
            __float_as_uint(y1) == __float_as_uint(cand.y)) {
            // verify pass already handled this chunk with the exact entry
            float2 e = g_flag[k] ? g_exit[k] : g_exit2[k];
            y0 = e.x; y1 = e.y;
            continue;
        }
        // entry differs from what verify used: replay fully, rewrite outputs
        const float4* xp = x + (size_t)k * L;
        float2*       op = out + (size_t)k * L;
        for (int s = 0; s < L; ++s) {
            step_from_x(xp[s], m, d, B, y0, y1);
            op[s] = sigmoid2(y0, y1, W20, W21, W22, W23, bo0, bo1);
        }
    }
}

// ---------------- launch -----------------------------------------------------
extern "C" void kernel_launch(void* const* d_in, const int* in_sizes, int n_in,
                              void* d_out, int out_size) {
    const float* x  = (const float*)d_in[0];
    const float* W1 = (const float*)d_in[1];
    const float* b1 = (const float*)d_in[2];
    const float* Wd = (const float*)d_in[3];
    const float* bd = (const float*)d_in[4];
    const float* W2 = (const float*)d_in[5];
    const float* b2 = (const float*)d_in[6];
    (void)in_sizes; (void)n_in; (void)out_size;

    k1_scan  <<<C / KPB, TPB>>>((const float4*)x, W1, b1, Wd, bd, W2, b2, (float2*)d_out);
    k2_verify<<<C / 256, 256>>>((const float4*)x, W1, b1, Wd, bd, W2, b2, (float2*)d_out);
    k3_cleanup<<<1, 32>>>      ((const float4*)x, W1, b1, Wd, bd, W2, b2, (float2*)d_out);
}